// round 5
// baseline (speedup 1.0000x reference)
#include <cuda_runtime.h>
#include <math.h>

#define HW 128
#define NPIX (HW*HW)
#define NF 512
#define NP 256
#define SIGMAINV 7000.0f
#define BBOX_M 0.06f
#define DLB_T 0.055f

// Per-face precomputed tables (AoS of float4, 4 per face each).
// hot:  [0]=bbox(xmin-m, xmax+m, ymin-m, ymax+m) (poisoned if !front||!valid)
//       [1]=(x0,y0,x1,y1)  [2]=(x2,y2,invden,0)  [3]=(h0,h1,h2,0)
// cold: [0]=(z0,z1,z2,0)   [1..3]=vertex colors (r,g,b,0)
__device__ float4 g_hot[NF * 4];
__device__ float4 g_cold[NF * 4];

__global__ __launch_bounds__(256)
void preproc_kernel(const float* __restrict__ pts,
                    const float* __restrict__ cols,
                    const float* __restrict__ rot,
                    const float* __restrict__ cpos,
                    const float* __restrict__ proj,
                    const int* __restrict__ faces,
                    float* __restrict__ out) {
    int f = blockIdx.x * blockDim.x + threadIdx.x;
    if (f >= NF) return;

    float r00 = rot[0], r01 = rot[1], r02 = rot[2];
    float r10 = rot[3], r11 = rot[4], r12 = rot[5];
    float r20 = rot[6], r21 = rot[7], r22 = rot[8];
    float cx = cpos[0], cy = cpos[1], cz = cpos[2];
    float pr0 = proj[0], pr1 = proj[1], pr2 = proj[2];

    int idx[3];
    idx[0] = faces[f * 3 + 0];
    idx[1] = faces[f * 3 + 1];
    idx[2] = faces[f * 3 + 2];

    float camx[3], camy[3], camz[3], sx[3], sy[3];
#pragma unroll
    for (int k = 0; k < 3; k++) {
        float qx = pts[idx[k] * 3 + 0] - cx;
        float qy = pts[idx[k] * 3 + 1] - cy;
        float qz = pts[idx[k] * 3 + 2] - cz;
        float X = qx * r00 + qy * r01 + qz * r02;
        float Y = qx * r10 + qy * r11 + qz * r12;
        float Z = qx * r20 + qy * r21 + qz * r22;
        camx[k] = X; camy[k] = Y; camz[k] = Z;
        sx[k] = (X * pr0) / (Z * pr2);
        sy[k] = (Y * pr1) / (Z * pr2);
    }

    // normal in camera space (matches reference cross(pf1-pf0, pf2-pf0))
    float e1x = camx[1] - camx[0], e1y = camy[1] - camy[0], e1z = camz[1] - camz[0];
    float e2x = camx[2] - camx[0], e2y = camy[2] - camy[0], e2z = camz[2] - camz[0];
    float nx = e1y * e2z - e1z * e2y;
    float ny = e1z * e2x - e1x * e2z;
    float nz = e1x * e2y - e1y * e2x;
    float nlen = sqrtf(nx * nx + ny * ny + nz * nz + 1e-8f);
    float ninv = 1.0f / (nlen + 1e-15f);
    out[NPIX * 4 + f * 3 + 0] = nx * ninv;
    out[NPIX * 4 + f * 3 + 1] = ny * ninv;
    out[NPIX * 4 + f * 3 + 2] = nz * ninv;

    float area = (sx[1] - sx[0]) * (sy[2] - sy[0]) - (sx[2] - sx[0]) * (sy[1] - sy[0]);
    bool ok = (nz > 0.0f) && (fabsf(area) > 1e-10f);

    float4 bb;
    if (ok) {
        bb.x = fminf(fminf(sx[0], sx[1]), sx[2]) - BBOX_M;
        bb.y = fmaxf(fmaxf(sx[0], sx[1]), sx[2]) + BBOX_M;
        bb.z = fminf(fminf(sy[0], sy[1]), sy[2]) - BBOX_M;
        bb.w = fmaxf(fmaxf(sy[0], sy[1]), sy[2]) + BBOX_M;
    } else {
        bb = make_float4(1e30f, -1e30f, 1e30f, -1e30f);  // always rejected
    }

    float aabs = fabsf(area);
    float L0 = sqrtf((sx[2] - sx[1]) * (sx[2] - sx[1]) + (sy[2] - sy[1]) * (sy[2] - sy[1]));
    float L1 = sqrtf((sx[0] - sx[2]) * (sx[0] - sx[2]) + (sy[0] - sy[2]) * (sy[0] - sy[2]));
    float L2 = sqrtf((sx[1] - sx[0]) * (sx[1] - sx[0]) + (sy[1] - sy[0]) * (sy[1] - sy[0]));
    float h0 = aabs / fmaxf(L0, 1e-20f);
    float h1 = aabs / fmaxf(L1, 1e-20f);
    float h2 = aabs / fmaxf(L2, 1e-20f);

    g_hot[f * 4 + 0] = bb;
    g_hot[f * 4 + 1] = make_float4(sx[0], sy[0], sx[1], sy[1]);
    g_hot[f * 4 + 2] = make_float4(sx[2], sy[2], ok ? (1.0f / area) : 0.0f, 0.0f);
    g_hot[f * 4 + 3] = make_float4(h0, h1, h2, 0.0f);

    g_cold[f * 4 + 0] = make_float4(camz[0], camz[1], camz[2], 0.0f);
    g_cold[f * 4 + 1] = make_float4(cols[idx[0] * 3 + 0], cols[idx[0] * 3 + 1], cols[idx[0] * 3 + 2], 0.0f);
    g_cold[f * 4 + 2] = make_float4(cols[idx[1] * 3 + 0], cols[idx[1] * 3 + 1], cols[idx[1] * 3 + 2], 0.0f);
    g_cold[f * 4 + 3] = make_float4(cols[idx[2] * 3 + 0], cols[idx[2] * 3 + 1], cols[idx[2] * 3 + 2], 0.0f);
}

__device__ __forceinline__ float seg_d2(float px, float py, float ax, float ay,
                                        float bx, float by) {
    float abx = bx - ax, aby = by - ay;
    float apx = px - ax, apy = py - ay;
    float t = (apx * abx + apy * aby) / (abx * abx + aby * aby + 1e-10f);
    t = fminf(fmaxf(t, 0.0f), 1.0f);
    float dx = apx - t * abx;
    float dy = apy - t * aby;
    return dx * dx + dy * dy;
}

// 8 pixels per warp, faces split x4 across lane groups (sub = lane>>3).
__global__ __launch_bounds__(128)
void raster_kernel(float* __restrict__ out) {
    int t = threadIdx.x;
    int lane = t & 31;
    int warp = t >> 5;
    int sub = lane >> 3;
    int pix = lane & 7;
    int p = blockIdx.x * 32 + warp * 8 + pix;
    int ix = p & (HW - 1);
    int iy = p >> 7;

    float px = (ix + 0.5f) * (2.0f / HW) - 1.0f;
    float py = 1.0f - (iy + 0.5f) * (2.0f / HW);

    int fbeg = sub * (NF / 4);
    int fend = fbeg + (NF / 4);

    float prodv = 1.0f;
    float zmin = 3.0e38f;
    float rr = 0.0f, gg = 0.0f, bc = 0.0f;

    for (int f = fbeg; f < fend; f++) {
        float4 bb = __ldg(&g_hot[f * 4 + 0]);
        if (px < bb.x || px > bb.y || py < bb.z || py > bb.w) continue;

        float4 v01 = __ldg(&g_hot[f * 4 + 1]);
        float4 v2i = __ldg(&g_hot[f * 4 + 2]);
        float w0 = ((v01.z - px) * (v2i.y - py) - (v2i.x - px) * (v01.w - py)) * v2i.z;
        float w1 = ((v2i.x - px) * (v01.y - py) - (v01.x - px) * (v2i.y - py)) * v2i.z;
        float w2 = 1.0f - w0 - w1;

        if (w0 >= 0.0f && w1 >= 0.0f && w2 >= 0.0f) {
            prodv = 0.0f;  // probf = exp(0) = 1 inside
            float4 zz = __ldg(&g_cold[f * 4 + 0]);
            float z = w0 * zz.x + w1 * zz.y + w2 * zz.z;
            if (z < zmin) {  // strict < keeps first occurrence (argmin semantics)
                zmin = z;
                float4 c0 = __ldg(&g_cold[f * 4 + 1]);
                float4 c1 = __ldg(&g_cold[f * 4 + 2]);
                float4 c2 = __ldg(&g_cold[f * 4 + 3]);
                rr = w0 * c0.x + w1 * c1.x + w2 * c2.x;
                gg = w0 * c0.y + w1 * c1.y + w2 * c2.y;
                bc = w0 * c0.z + w1 * c1.z + w2 * c2.z;
            }
        } else if (prodv != 0.0f) {
            float4 hh = __ldg(&g_hot[f * 4 + 3]);
            // lower bound on distance to triangle; if > DLB_T, (1-probf)==1.0f exactly
            float dlb = fmaxf(fmaxf(-w0 * hh.x, -w1 * hh.y), -w2 * hh.z);
            if (dlb < DLB_T) {
                float d2 = seg_d2(px, py, v01.x, v01.y, v01.z, v01.w);
                d2 = fminf(d2, seg_d2(px, py, v01.z, v01.w, v2i.x, v2i.y));
                d2 = fminf(d2, seg_d2(px, py, v2i.x, v2i.y, v01.x, v01.y));
                prodv *= (1.0f - expf(-d2 * SIGMAINV));
            }
        }
    }

    // Combine the 4 face-range partials (butterfly over sub groups).
    const unsigned m = 0xFFFFFFFFu;
    float z = zmin;
    int q = sub;
#pragma unroll
    for (int off = 8; off <= 16; off <<= 1) {
        float oz = __shfl_xor_sync(m, z, off);
        int oq = __shfl_xor_sync(m, q, off);
        float orr = __shfl_xor_sync(m, rr, off);
        float ogg = __shfl_xor_sync(m, gg, off);
        float obc = __shfl_xor_sync(m, bc, off);
        float op = __shfl_xor_sync(m, prodv, off);
        prodv *= op;
        bool take = (oz < z) || (oz == z && oq < q);  // lower face range wins ties
        if (take) { z = oz; q = oq; rr = orr; gg = ogg; bc = obc; }
    }

    if (sub == 0) {
        out[p * 3 + 0] = rr;
        out[p * 3 + 1] = gg;
        out[p * 3 + 2] = bc;
        out[NPIX * 3 + p] = 1.0f - prodv;
    }
}

extern "C" void kernel_launch(void* const* d_in, const int* in_sizes, int n_in,
                              void* d_out, int out_size) {
    const float* pts  = (const float*)d_in[0];
    const float* cols = (const float*)d_in[1];
    const float* rot  = (const float*)d_in[2];
    const float* cpos = (const float*)d_in[3];
    const float* proj = (const float*)d_in[4];
    const int*   fcs  = (const int*)d_in[5];
    float* out = (float*)d_out;

    preproc_kernel<<<2, 256>>>(pts, cols, rot, cpos, proj, fcs, out);
    raster_kernel<<<NPIX / 32, 128>>>(out);
}

// round 6
// speedup vs baseline: 1.5302x; 1.5302x over previous
#include <cuda_runtime.h>
#include <math.h>

#define HW 128
#define NPIX (HW*HW)
#define NF 512
#define NP 256
#define SIGMAINV 7000.0f
#define BBOX_M 0.06f
#define DLB_T 0.055f
#define NSUB 8
#define FPS (NF / NSUB)   /* faces per sub-group = 64 */

// Per-face precomputed tables (AoS of float4, 4 per face each).
// hot:  [0]=bbox(xmin-m, xmax+m, ymin-m, ymax+m) (poisoned if !front||!valid)
//       [1]=(x0,y0,x1,y1)  [2]=(x2,y2,invden,0)  [3]=(h0,h1,h2,0)
// cold: [0]=(z0,z1,z2,0)   [1..3]=vertex colors (r,g,b,0)
__device__ float4 g_hot[NF * 4];
__device__ float4 g_cold[NF * 4];

__global__ __launch_bounds__(256)
void preproc_kernel(const float* __restrict__ pts,
                    const float* __restrict__ cols,
                    const float* __restrict__ rot,
                    const float* __restrict__ cpos,
                    const float* __restrict__ proj,
                    const int* __restrict__ faces,
                    float* __restrict__ out) {
    int f = blockIdx.x * blockDim.x + threadIdx.x;
    if (f >= NF) return;

    float r00 = rot[0], r01 = rot[1], r02 = rot[2];
    float r10 = rot[3], r11 = rot[4], r12 = rot[5];
    float r20 = rot[6], r21 = rot[7], r22 = rot[8];
    float cx = cpos[0], cy = cpos[1], cz = cpos[2];
    float pr0 = proj[0], pr1 = proj[1], pr2 = proj[2];

    int idx[3];
    idx[0] = faces[f * 3 + 0];
    idx[1] = faces[f * 3 + 1];
    idx[2] = faces[f * 3 + 2];

    float camx[3], camy[3], camz[3], sx[3], sy[3];
#pragma unroll
    for (int k = 0; k < 3; k++) {
        float qx = pts[idx[k] * 3 + 0] - cx;
        float qy = pts[idx[k] * 3 + 1] - cy;
        float qz = pts[idx[k] * 3 + 2] - cz;
        float X = qx * r00 + qy * r01 + qz * r02;
        float Y = qx * r10 + qy * r11 + qz * r12;
        float Z = qx * r20 + qy * r21 + qz * r22;
        camx[k] = X; camy[k] = Y; camz[k] = Z;
        sx[k] = (X * pr0) / (Z * pr2);
        sy[k] = (Y * pr1) / (Z * pr2);
    }

    // normal in camera space (matches reference cross(pf1-pf0, pf2-pf0))
    float e1x = camx[1] - camx[0], e1y = camy[1] - camy[0], e1z = camz[1] - camz[0];
    float e2x = camx[2] - camx[0], e2y = camy[2] - camy[0], e2z = camz[2] - camz[0];
    float nx = e1y * e2z - e1z * e2y;
    float ny = e1z * e2x - e1x * e2z;
    float nz = e1x * e2y - e1y * e2x;
    float nlen = sqrtf(nx * nx + ny * ny + nz * nz + 1e-8f);
    float ninv = 1.0f / (nlen + 1e-15f);
    out[NPIX * 4 + f * 3 + 0] = nx * ninv;
    out[NPIX * 4 + f * 3 + 1] = ny * ninv;
    out[NPIX * 4 + f * 3 + 2] = nz * ninv;

    float area = (sx[1] - sx[0]) * (sy[2] - sy[0]) - (sx[2] - sx[0]) * (sy[1] - sy[0]);
    bool ok = (nz > 0.0f) && (fabsf(area) > 1e-10f);

    float4 bb;
    if (ok) {
        bb.x = fminf(fminf(sx[0], sx[1]), sx[2]) - BBOX_M;
        bb.y = fmaxf(fmaxf(sx[0], sx[1]), sx[2]) + BBOX_M;
        bb.z = fminf(fminf(sy[0], sy[1]), sy[2]) - BBOX_M;
        bb.w = fmaxf(fmaxf(sy[0], sy[1]), sy[2]) + BBOX_M;
    } else {
        bb = make_float4(1e30f, -1e30f, 1e30f, -1e30f);  // always rejected
    }

    float aabs = fabsf(area);
    float L0 = sqrtf((sx[2] - sx[1]) * (sx[2] - sx[1]) + (sy[2] - sy[1]) * (sy[2] - sy[1]));
    float L1 = sqrtf((sx[0] - sx[2]) * (sx[0] - sx[2]) + (sy[0] - sy[2]) * (sy[0] - sy[2]));
    float L2 = sqrtf((sx[1] - sx[0]) * (sx[1] - sx[0]) + (sy[1] - sy[0]) * (sy[1] - sy[0]));
    float h0 = aabs / fmaxf(L0, 1e-20f);
    float h1 = aabs / fmaxf(L1, 1e-20f);
    float h2 = aabs / fmaxf(L2, 1e-20f);

    g_hot[f * 4 + 0] = bb;
    g_hot[f * 4 + 1] = make_float4(sx[0], sy[0], sx[1], sy[1]);
    g_hot[f * 4 + 2] = make_float4(sx[2], sy[2], ok ? (1.0f / area) : 0.0f, 0.0f);
    g_hot[f * 4 + 3] = make_float4(h0, h1, h2, 0.0f);

    g_cold[f * 4 + 0] = make_float4(camz[0], camz[1], camz[2], 0.0f);
    g_cold[f * 4 + 1] = make_float4(cols[idx[0] * 3 + 0], cols[idx[0] * 3 + 1], cols[idx[0] * 3 + 2], 0.0f);
    g_cold[f * 4 + 2] = make_float4(cols[idx[1] * 3 + 0], cols[idx[1] * 3 + 1], cols[idx[1] * 3 + 2], 0.0f);
    g_cold[f * 4 + 3] = make_float4(cols[idx[2] * 3 + 0], cols[idx[2] * 3 + 1], cols[idx[2] * 3 + 2], 0.0f);
}

__device__ __forceinline__ float seg_d2(float px, float py, float ax, float ay,
                                        float bx, float by) {
    float abx = bx - ax, aby = by - ay;
    float apx = px - ax, apy = py - ay;
    float t = (apx * abx + apy * aby) / (abx * abx + aby * aby + 1e-10f);
    t = fminf(fmaxf(t, 0.0f), 1.0f);
    float dx = apx - t * abx;
    float dy = apy - t * aby;
    return dx * dx + dy * dy;
}

// Heavy per-face body; bbox already tested by caller.
__device__ __forceinline__ void face_body(int f, float px, float py,
                                          float& prodv, float& zmin,
                                          float& rr, float& gg, float& bc) {
    float4 v01 = __ldg(&g_hot[f * 4 + 1]);
    float4 v2i = __ldg(&g_hot[f * 4 + 2]);
    float w0 = ((v01.z - px) * (v2i.y - py) - (v2i.x - px) * (v01.w - py)) * v2i.z;
    float w1 = ((v2i.x - px) * (v01.y - py) - (v01.x - px) * (v2i.y - py)) * v2i.z;
    float w2 = 1.0f - w0 - w1;

    if (w0 >= 0.0f && w1 >= 0.0f && w2 >= 0.0f) {
        prodv = 0.0f;  // probf = exp(0) = 1 inside
        float4 zz = __ldg(&g_cold[f * 4 + 0]);
        float z = w0 * zz.x + w1 * zz.y + w2 * zz.z;
        if (z < zmin) {  // strict < keeps first occurrence (argmin semantics)
            zmin = z;
            float4 c0 = __ldg(&g_cold[f * 4 + 1]);
            float4 c1 = __ldg(&g_cold[f * 4 + 2]);
            float4 c2 = __ldg(&g_cold[f * 4 + 3]);
            rr = w0 * c0.x + w1 * c1.x + w2 * c2.x;
            gg = w0 * c0.y + w1 * c1.y + w2 * c2.y;
            bc = w0 * c0.z + w1 * c1.z + w2 * c2.z;
        }
    } else if (prodv != 0.0f) {
        float4 hh = __ldg(&g_hot[f * 4 + 3]);
        // lower bound on distance to triangle; if > DLB_T, (1-probf)==1.0f exactly
        float dlb = fmaxf(fmaxf(-w0 * hh.x, -w1 * hh.y), -w2 * hh.z);
        if (dlb < DLB_T) {
            float d2 = seg_d2(px, py, v01.x, v01.y, v01.z, v01.w);
            d2 = fminf(d2, seg_d2(px, py, v01.z, v01.w, v2i.x, v2i.y));
            d2 = fminf(d2, seg_d2(px, py, v2i.x, v2i.y, v01.x, v01.y));
            prodv *= (1.0f - expf(-d2 * SIGMAINV));
        }
    }
}

// 4 pixels per warp, faces split x8 across lane groups (sub = lane>>2).
// Per iteration-block, 4 bbox loads are batched up front (MLP=4).
__global__ __launch_bounds__(256)
void raster_kernel(float* __restrict__ out) {
    int t = threadIdx.x;
    int lane = t & 31;
    int warp = t >> 5;          // 0..7
    int sub = lane >> 2;        // 0..7
    int pix = lane & 3;         // 0..3
    int p = blockIdx.x * 32 + warp * 4 + pix;
    int ix = p & (HW - 1);
    int iy = p >> 7;

    float px = (ix + 0.5f) * (2.0f / HW) - 1.0f;
    float py = 1.0f - (iy + 0.5f) * (2.0f / HW);

    int fbeg = sub * FPS;

    float prodv = 1.0f;
    float zmin = 3.0e38f;
    float rr = 0.0f, gg = 0.0f, bc = 0.0f;

#pragma unroll 1
    for (int f0 = fbeg; f0 < fbeg + FPS; f0 += 4) {
        // batch the 4 loop-independent bbox loads (raise MLP, hide L1/L2 latency)
        float4 b0 = __ldg(&g_hot[(f0 + 0) * 4]);
        float4 b1 = __ldg(&g_hot[(f0 + 1) * 4]);
        float4 b2 = __ldg(&g_hot[(f0 + 2) * 4]);
        float4 b3 = __ldg(&g_hot[(f0 + 3) * 4]);

        bool h0 = !(px < b0.x || px > b0.y || py < b0.z || py > b0.w);
        bool h1 = !(px < b1.x || px > b1.y || py < b1.z || py > b1.w);
        bool h2 = !(px < b2.x || px > b2.y || py < b2.z || py > b2.w);
        bool h3 = !(px < b3.x || px > b3.y || py < b3.z || py > b3.w);

        if (h0) face_body(f0 + 0, px, py, prodv, zmin, rr, gg, bc);
        if (h1) face_body(f0 + 1, px, py, prodv, zmin, rr, gg, bc);
        if (h2) face_body(f0 + 2, px, py, prodv, zmin, rr, gg, bc);
        if (h3) face_body(f0 + 3, px, py, prodv, zmin, rr, gg, bc);
    }

    // Combine the 8 face-range partials (butterfly over sub groups).
    const unsigned m = 0xFFFFFFFFu;
    float z = zmin;
    int q = sub;
#pragma unroll
    for (int off = 4; off <= 16; off <<= 1) {
        float oz = __shfl_xor_sync(m, z, off);
        int oq = __shfl_xor_sync(m, q, off);
        float orr = __shfl_xor_sync(m, rr, off);
        float ogg = __shfl_xor_sync(m, gg, off);
        float obc = __shfl_xor_sync(m, bc, off);
        float op = __shfl_xor_sync(m, prodv, off);
        prodv *= op;
        bool take = (oz < z) || (oz == z && oq < q);  // lower face range wins ties
        if (take) { z = oz; q = oq; rr = orr; gg = ogg; bc = obc; }
    }

    if (sub == 0) {
        out[p * 3 + 0] = rr;
        out[p * 3 + 1] = gg;
        out[p * 3 + 2] = bc;
        out[NPIX * 3 + p] = 1.0f - prodv;
    }
}

extern "C" void kernel_launch(void* const* d_in, const int* in_sizes, int n_in,
                              void* d_out, int out_size) {
    const float* pts  = (const float*)d_in[0];
    const float* cols = (const float*)d_in[1];
    const float* rot  = (const float*)d_in[2];
    const float* cpos = (const float*)d_in[3];
    const float* proj = (const float*)d_in[4];
    const int*   fcs  = (const int*)d_in[5];
    float* out = (float*)d_out;

    preproc_kernel<<<2, 256>>>(pts, cols, rot, cpos, proj, fcs, out);
    raster_kernel<<<NPIX / 32, 256>>>(out);
}

// round 7
// speedup vs baseline: 2.0994x; 1.3720x over previous
#include <cuda_runtime.h>
#include <math.h>

#define HW 128
#define NPIX (HW*HW)
#define NF 512
#define NP 256
#define SIGMAINV 7000.0f
#define BBOX_M 0.06f
#define DLB_T 0.055f

// Per-face precomputed tables (AoS of float4, 4 per face each).
// hot:  [0]=bbox(xmin-m, xmax+m, ymin-m, ymax+m) (poisoned if !front||!valid)
//       [1]=(x0,y0,x1,y1)  [2]=(x2,y2,invden,0)  [3]=(h0,h1,h2,0)
// cold: [0]=(z0,z1,z2,0)   [1..3]=vertex colors (r,g,b,0)
__device__ float4 g_hot[NF * 4];
__device__ float4 g_cold[NF * 4];

__global__ __launch_bounds__(256)
void preproc_kernel(const float* __restrict__ pts,
                    const float* __restrict__ cols,
                    const float* __restrict__ rot,
                    const float* __restrict__ cpos,
                    const float* __restrict__ proj,
                    const int* __restrict__ faces,
                    float* __restrict__ out) {
    int f = blockIdx.x * blockDim.x + threadIdx.x;
    if (f >= NF) return;

    float r00 = rot[0], r01 = rot[1], r02 = rot[2];
    float r10 = rot[3], r11 = rot[4], r12 = rot[5];
    float r20 = rot[6], r21 = rot[7], r22 = rot[8];
    float cx = cpos[0], cy = cpos[1], cz = cpos[2];
    float pr0 = proj[0], pr1 = proj[1], pr2 = proj[2];

    int idx[3];
    idx[0] = faces[f * 3 + 0];
    idx[1] = faces[f * 3 + 1];
    idx[2] = faces[f * 3 + 2];

    float camx[3], camy[3], camz[3], sx[3], sy[3];
#pragma unroll
    for (int k = 0; k < 3; k++) {
        float qx = pts[idx[k] * 3 + 0] - cx;
        float qy = pts[idx[k] * 3 + 1] - cy;
        float qz = pts[idx[k] * 3 + 2] - cz;
        float X = qx * r00 + qy * r01 + qz * r02;
        float Y = qx * r10 + qy * r11 + qz * r12;
        float Z = qx * r20 + qy * r21 + qz * r22;
        camx[k] = X; camy[k] = Y; camz[k] = Z;
        sx[k] = (X * pr0) / (Z * pr2);
        sy[k] = (Y * pr1) / (Z * pr2);
    }

    // normal in camera space (matches reference cross(pf1-pf0, pf2-pf0))
    float e1x = camx[1] - camx[0], e1y = camy[1] - camy[0], e1z = camz[1] - camz[0];
    float e2x = camx[2] - camx[0], e2y = camy[2] - camy[0], e2z = camz[2] - camz[0];
    float nx = e1y * e2z - e1z * e2y;
    float ny = e1z * e2x - e1x * e2z;
    float nz = e1x * e2y - e1y * e2x;
    float nlen = sqrtf(nx * nx + ny * ny + nz * nz + 1e-8f);
    float ninv = 1.0f / (nlen + 1e-15f);
    out[NPIX * 4 + f * 3 + 0] = nx * ninv;
    out[NPIX * 4 + f * 3 + 1] = ny * ninv;
    out[NPIX * 4 + f * 3 + 2] = nz * ninv;

    float area = (sx[1] - sx[0]) * (sy[2] - sy[0]) - (sx[2] - sx[0]) * (sy[1] - sy[0]);
    bool ok = (nz > 0.0f) && (fabsf(area) > 1e-10f);

    float4 bb;
    if (ok) {
        bb.x = fminf(fminf(sx[0], sx[1]), sx[2]) - BBOX_M;
        bb.y = fmaxf(fmaxf(sx[0], sx[1]), sx[2]) + BBOX_M;
        bb.z = fminf(fminf(sy[0], sy[1]), sy[2]) - BBOX_M;
        bb.w = fmaxf(fmaxf(sy[0], sy[1]), sy[2]) + BBOX_M;
    } else {
        bb = make_float4(1e30f, -1e30f, 1e30f, -1e30f);  // always rejected
    }

    float aabs = fabsf(area);
    float L0 = sqrtf((sx[2] - sx[1]) * (sx[2] - sx[1]) + (sy[2] - sy[1]) * (sy[2] - sy[1]));
    float L1 = sqrtf((sx[0] - sx[2]) * (sx[0] - sx[2]) + (sy[0] - sy[2]) * (sy[0] - sy[2]));
    float L2 = sqrtf((sx[1] - sx[0]) * (sx[1] - sx[0]) + (sy[1] - sy[0]) * (sy[1] - sy[0]));
    float h0 = aabs / fmaxf(L0, 1e-20f);
    float h1 = aabs / fmaxf(L1, 1e-20f);
    float h2 = aabs / fmaxf(L2, 1e-20f);

    g_hot[f * 4 + 0] = bb;
    g_hot[f * 4 + 1] = make_float4(sx[0], sy[0], sx[1], sy[1]);
    g_hot[f * 4 + 2] = make_float4(sx[2], sy[2], ok ? (1.0f / area) : 0.0f, 0.0f);
    g_hot[f * 4 + 3] = make_float4(h0, h1, h2, 0.0f);

    g_cold[f * 4 + 0] = make_float4(camz[0], camz[1], camz[2], 0.0f);
    g_cold[f * 4 + 1] = make_float4(cols[idx[0] * 3 + 0], cols[idx[0] * 3 + 1], cols[idx[0] * 3 + 2], 0.0f);
    g_cold[f * 4 + 2] = make_float4(cols[idx[1] * 3 + 0], cols[idx[1] * 3 + 1], cols[idx[1] * 3 + 2], 0.0f);
    g_cold[f * 4 + 3] = make_float4(cols[idx[2] * 3 + 0], cols[idx[2] * 3 + 1], cols[idx[2] * 3 + 2], 0.0f);
}

__device__ __forceinline__ float seg_d2(float px, float py, float ax, float ay,
                                        float bx, float by) {
    float abx = bx - ax, aby = by - ay;
    float apx = px - ax, apy = py - ay;
    float t = (apx * abx + apy * aby) / (abx * abx + aby * aby + 1e-10f);
    t = fminf(fmaxf(t, 0.0f), 1.0f);
    float dx = apx - t * abx;
    float dy = apy - t * aby;
    return dx * dx + dy * dy;
}

// Block = 256 threads = 8 warps, all covering ONE 8x4-pixel patch (lane = pixel).
// Phase 1: build 512-bit face mask for the patch via 2 ballots per warp.
// Phase 2: warp w processes mask words {w, 8+w}; faces are warp-uniform.
// Phase 3: smem reduction across the 8 warps; warp 0 fetches winner colors + writes.
__global__ __launch_bounds__(256)
void raster_kernel(float* __restrict__ out) {
    __shared__ float s_z[8][32], s_w0[8][32], s_w1[8][32], s_w2[8][32], s_p[8][32];
    __shared__ int s_f[8][32];

    int t = threadIdx.x;
    int lane = t & 31;
    int wid = t >> 5;
    int b = blockIdx.x;
    int px0 = (b & 15) * 8;     // 16 patches across
    int py0 = (b >> 4) * 4;     // 32 patch-rows
    int ix = px0 + (lane & 7);
    int iy = py0 + (lane >> 3);

    float px = (ix + 0.5f) * (2.0f / HW) - 1.0f;
    float py = 1.0f - (iy + 0.5f) * (2.0f / HW);

    // patch NDC bounds (pixel centers)
    float xmn = (px0 + 0.5f) * (2.0f / HW) - 1.0f;
    float xmx = (px0 + 7.5f) * (2.0f / HW) - 1.0f;
    float ymx = 1.0f - (py0 + 0.5f) * (2.0f / HW);
    float ymn = 1.0f - (py0 + 3.5f) * (2.0f / HW);

    // Phase 1: patch-vs-face-bbox mask. Warp w, iter i covers faces
    // [i*256 + w*32, +32) -> mask word i*8+w, kept in registers.
    unsigned words[2];
#pragma unroll
    for (int i = 0; i < 2; i++) {
        int f = i * 256 + wid * 32 + lane;
        float4 bb = __ldg(&g_hot[f * 4]);
        bool ov = (bb.x <= xmx) && (bb.y >= xmn) && (bb.z <= ymx) && (bb.w >= ymn);
        words[i] = __ballot_sync(0xFFFFFFFFu, ov);
    }

    float prodv = 1.0f;
    float zb = 3.0e38f;
    float w0b = 0.0f, w1b = 0.0f, w2b = 0.0f;
    int fb = 0x7FFFFFFF;

    // Phase 2: process surviving faces, warp-uniform.
#pragma unroll
    for (int i = 0; i < 2; i++) {
        unsigned m = words[i];
        int base = (i * 8 + wid) * 32;
        while (m) {
            int bit = __ffs(m) - 1;
            m &= m - 1;
            int f = base + bit;
            float4 bb = __ldg(&g_hot[f * 4 + 0]);
            bool hit = (px >= bb.x) && (px <= bb.y) && (py >= bb.z) && (py <= bb.w);
            if (!__any_sync(0xFFFFFFFFu, hit)) continue;

            float4 v01 = __ldg(&g_hot[f * 4 + 1]);
            float4 v2i = __ldg(&g_hot[f * 4 + 2]);
            float w0 = ((v01.z - px) * (v2i.y - py) - (v2i.x - px) * (v01.w - py)) * v2i.z;
            float w1 = ((v2i.x - px) * (v01.y - py) - (v01.x - px) * (v2i.y - py)) * v2i.z;
            float w2 = 1.0f - w0 - w1;

            if (w0 >= 0.0f && w1 >= 0.0f && w2 >= 0.0f) {
                prodv = 0.0f;  // probf = 1 inside
                float4 zz = __ldg(&g_cold[f * 4 + 0]);
                float z = w0 * zz.x + w1 * zz.y + w2 * zz.z;
                // argmin-first semantics: smaller z, ties -> smaller face index
                if (z < zb || (z == zb && f < fb)) {
                    zb = z; fb = f; w0b = w0; w1b = w1; w2b = w2;
                }
            } else if (hit && prodv != 0.0f) {
                float4 hh = __ldg(&g_hot[f * 4 + 3]);
                // lower bound on distance; if > DLB_T, (1-probf)==1.0f exactly
                float dlb = fmaxf(fmaxf(-w0 * hh.x, -w1 * hh.y), -w2 * hh.z);
                if (dlb < DLB_T) {
                    float d2 = seg_d2(px, py, v01.x, v01.y, v01.z, v01.w);
                    d2 = fminf(d2, seg_d2(px, py, v01.z, v01.w, v2i.x, v2i.y));
                    d2 = fminf(d2, seg_d2(px, py, v2i.x, v2i.y, v01.x, v01.y));
                    prodv *= (1.0f - expf(-d2 * SIGMAINV));
                }
            }
        }
    }

    // Phase 3: combine the 8 per-warp partials (lane = pixel).
    s_z[wid][lane] = zb;
    s_f[wid][lane] = fb;
    s_w0[wid][lane] = w0b;
    s_w1[wid][lane] = w1b;
    s_w2[wid][lane] = w2b;
    s_p[wid][lane] = prodv;
    __syncthreads();

    if (wid == 0) {
#pragma unroll
        for (int k = 1; k < 8; k++) {
            float oz = s_z[k][lane];
            int of = s_f[k][lane];
            prodv *= s_p[k][lane];
            if (oz < zb || (oz == zb && of < fb)) {
                zb = oz; fb = of;
                w0b = s_w0[k][lane];
                w1b = s_w1[k][lane];
                w2b = s_w2[k][lane];
            }
        }

        float rr = 0.0f, gg = 0.0f, bc = 0.0f;
        if (fb != 0x7FFFFFFF) {
            float4 c0 = __ldg(&g_cold[fb * 4 + 1]);
            float4 c1 = __ldg(&g_cold[fb * 4 + 2]);
            float4 c2 = __ldg(&g_cold[fb * 4 + 3]);
            rr = w0b * c0.x + w1b * c1.x + w2b * c2.x;
            gg = w0b * c0.y + w1b * c1.y + w2b * c2.y;
            bc = w0b * c0.z + w1b * c1.z + w2b * c2.z;
        }

        int p = iy * HW + ix;
        out[p * 3 + 0] = rr;
        out[p * 3 + 1] = gg;
        out[p * 3 + 2] = bc;
        out[NPIX * 3 + p] = 1.0f - prodv;
    }
}

extern "C" void kernel_launch(void* const* d_in, const int* in_sizes, int n_in,
                              void* d_out, int out_size) {
    const float* pts  = (const float*)d_in[0];
    const float* cols = (const float*)d_in[1];
    const float* rot  = (const float*)d_in[2];
    const float* cpos = (const float*)d_in[3];
    const float* proj = (const float*)d_in[4];
    const int*   fcs  = (const int*)d_in[5];
    float* out = (float*)d_out;

    preproc_kernel<<<2, 256>>>(pts, cols, rot, cpos, proj, fcs, out);
    raster_kernel<<<NPIX / 32, 256>>>(out);
}

// round 8
// speedup vs baseline: 2.1315x; 1.0153x over previous
#include <cuda_runtime.h>
#include <math.h>

#define HW 128
#define NPIX (HW*HW)
#define NF 512
#define NP 256
#define SIGMAINV 7000.0f
#define BBOX_M 0.06f
#define DLB_T 0.055f

// Per-face precomputed tables (AoS of float4, 4 per face each).
// hot:  [0]=bbox(xmin-m, xmax+m, ymin-m, ymax+m) (poisoned if !front||!valid)
//       [1]=(x0,y0,x1,y1)  [2]=(x2,y2,invden,0)  [3]=(h0,h1,h2,0)
// cold: [0]=(z0,z1,z2,0)   [1..3]=vertex colors (r,g,b,0)
__device__ float4 g_hot[NF * 4];
__device__ float4 g_cold[NF * 4];

__global__ __launch_bounds__(256)
void preproc_kernel(const float* __restrict__ pts,
                    const float* __restrict__ cols,
                    const float* __restrict__ rot,
                    const float* __restrict__ cpos,
                    const float* __restrict__ proj,
                    const int* __restrict__ faces,
                    float* __restrict__ out) {
    int f = blockIdx.x * blockDim.x + threadIdx.x;
    if (f >= NF) return;

    float r00 = rot[0], r01 = rot[1], r02 = rot[2];
    float r10 = rot[3], r11 = rot[4], r12 = rot[5];
    float r20 = rot[6], r21 = rot[7], r22 = rot[8];
    float cx = cpos[0], cy = cpos[1], cz = cpos[2];
    float pr0 = proj[0], pr1 = proj[1], pr2 = proj[2];

    int idx[3];
    idx[0] = faces[f * 3 + 0];
    idx[1] = faces[f * 3 + 1];
    idx[2] = faces[f * 3 + 2];

    float camx[3], camy[3], camz[3], sx[3], sy[3];
#pragma unroll
    for (int k = 0; k < 3; k++) {
        float qx = pts[idx[k] * 3 + 0] - cx;
        float qy = pts[idx[k] * 3 + 1] - cy;
        float qz = pts[idx[k] * 3 + 2] - cz;
        float X = qx * r00 + qy * r01 + qz * r02;
        float Y = qx * r10 + qy * r11 + qz * r12;
        float Z = qx * r20 + qy * r21 + qz * r22;
        camx[k] = X; camy[k] = Y; camz[k] = Z;
        sx[k] = (X * pr0) / (Z * pr2);
        sy[k] = (Y * pr1) / (Z * pr2);
    }

    // normal in camera space (matches reference cross(pf1-pf0, pf2-pf0))
    float e1x = camx[1] - camx[0], e1y = camy[1] - camy[0], e1z = camz[1] - camz[0];
    float e2x = camx[2] - camx[0], e2y = camy[2] - camy[0], e2z = camz[2] - camz[0];
    float nx = e1y * e2z - e1z * e2y;
    float ny = e1z * e2x - e1x * e2z;
    float nz = e1x * e2y - e1y * e2x;
    float nlen = sqrtf(nx * nx + ny * ny + nz * nz + 1e-8f);
    float ninv = 1.0f / (nlen + 1e-15f);
    out[NPIX * 4 + f * 3 + 0] = nx * ninv;
    out[NPIX * 4 + f * 3 + 1] = ny * ninv;
    out[NPIX * 4 + f * 3 + 2] = nz * ninv;

    float area = (sx[1] - sx[0]) * (sy[2] - sy[0]) - (sx[2] - sx[0]) * (sy[1] - sy[0]);
    bool ok = (nz > 0.0f) && (fabsf(area) > 1e-10f);

    float4 bb;
    if (ok) {
        bb.x = fminf(fminf(sx[0], sx[1]), sx[2]) - BBOX_M;
        bb.y = fmaxf(fmaxf(sx[0], sx[1]), sx[2]) + BBOX_M;
        bb.z = fminf(fminf(sy[0], sy[1]), sy[2]) - BBOX_M;
        bb.w = fmaxf(fmaxf(sy[0], sy[1]), sy[2]) + BBOX_M;
    } else {
        bb = make_float4(1e30f, -1e30f, 1e30f, -1e30f);  // always rejected
    }

    float aabs = fabsf(area);
    float L0 = sqrtf((sx[2] - sx[1]) * (sx[2] - sx[1]) + (sy[2] - sy[1]) * (sy[2] - sy[1]));
    float L1 = sqrtf((sx[0] - sx[2]) * (sx[0] - sx[2]) + (sy[0] - sy[2]) * (sy[0] - sy[2]));
    float L2 = sqrtf((sx[1] - sx[0]) * (sx[1] - sx[0]) + (sy[1] - sy[0]) * (sy[1] - sy[0]));
    float h0 = aabs / fmaxf(L0, 1e-20f);
    float h1 = aabs / fmaxf(L1, 1e-20f);
    float h2 = aabs / fmaxf(L2, 1e-20f);

    g_hot[f * 4 + 0] = bb;
    g_hot[f * 4 + 1] = make_float4(sx[0], sy[0], sx[1], sy[1]);
    g_hot[f * 4 + 2] = make_float4(sx[2], sy[2], ok ? (1.0f / area) : 0.0f, 0.0f);
    g_hot[f * 4 + 3] = make_float4(h0, h1, h2, 0.0f);

    g_cold[f * 4 + 0] = make_float4(camz[0], camz[1], camz[2], 0.0f);
    g_cold[f * 4 + 1] = make_float4(cols[idx[0] * 3 + 0], cols[idx[0] * 3 + 1], cols[idx[0] * 3 + 2], 0.0f);
    g_cold[f * 4 + 2] = make_float4(cols[idx[1] * 3 + 0], cols[idx[1] * 3 + 1], cols[idx[1] * 3 + 2], 0.0f);
    g_cold[f * 4 + 3] = make_float4(cols[idx[2] * 3 + 0], cols[idx[2] * 3 + 1], cols[idx[2] * 3 + 2], 0.0f);
}

__device__ __forceinline__ float seg_d2(float px, float py, float ax, float ay,
                                        float bx, float by) {
    float abx = bx - ax, aby = by - ay;
    float apx = px - ax, apy = py - ay;
    float t = (apx * abx + apy * aby) / (abx * abx + aby * aby + 1e-10f);
    t = fminf(fmaxf(t, 0.0f), 1.0f);
    float dx = apx - t * abx;
    float dy = apy - t * aby;
    return dx * dx + dy * dy;
}

// Block = 256 threads = 8 warps, one 8x4-pixel patch (lane = pixel).
// Phase 1: patch-vs-bbox ballot mask -> deterministic compaction into s_list.
// Phase 2: warps take list entries round-robin (balanced), software-pipelined.
// Phase 3: smem reduction; warp 0 fetches winner colors + writes.
__global__ __launch_bounds__(256)
void raster_kernel(float* __restrict__ out) {
    __shared__ unsigned s_words[16];
    __shared__ int s_cnt;
    __shared__ short s_list[NF];
    __shared__ float s_z[8][32], s_w0[8][32], s_w1[8][32], s_w2[8][32], s_p[8][32];
    __shared__ int s_f[8][32];

    int t = threadIdx.x;
    int lane = t & 31;
    int wid = t >> 5;
    int b = blockIdx.x;
    int px0 = (b & 15) * 8;     // 16 patches across
    int py0 = (b >> 4) * 4;     // 32 patch-rows
    int ix = px0 + (lane & 7);
    int iy = py0 + (lane >> 3);

    float px = (ix + 0.5f) * (2.0f / HW) - 1.0f;
    float py = 1.0f - (iy + 0.5f) * (2.0f / HW);

    // patch NDC bounds (pixel centers)
    float xmn = (px0 + 0.5f) * (2.0f / HW) - 1.0f;
    float xmx = (px0 + 7.5f) * (2.0f / HW) - 1.0f;
    float ymx = 1.0f - (py0 + 0.5f) * (2.0f / HW);
    float ymn = 1.0f - (py0 + 3.5f) * (2.0f / HW);

    // Phase 1: patch-vs-face-bbox ballots (thread tests 2 faces).
#pragma unroll
    for (int i = 0; i < 2; i++) {
        int f = i * 256 + t;
        float4 bb = __ldg(&g_hot[f * 4]);
        bool ov = (bb.x <= xmx) && (bb.y >= xmn) && (bb.z <= ymx) && (bb.w >= ymn);
        unsigned bal = __ballot_sync(0xFFFFFFFFu, ov);
        if (lane == 0) s_words[i * 8 + wid] = bal;
    }
    __syncthreads();

    // Deterministic compaction by warp 0: scan popcounts, expand bits in order.
    if (wid == 0) {
        unsigned wv = (lane < 16) ? s_words[lane] : 0u;
        int c = __popc(wv);
        int s = c;
#pragma unroll
        for (int off = 1; off < 32; off <<= 1) {
            int n = __shfl_up_sync(0xFFFFFFFFu, s, off);
            if (lane >= off) s += n;
        }
        if (lane == 15) s_cnt = s;
        if (lane < 16) {
            int pos = s - c;
            int base = lane * 32;
            unsigned m = wv;
            while (m) {
                int bit = __ffs(m) - 1;
                m &= m - 1;
                s_list[pos++] = (short)(base + bit);
            }
        }
    }
    __syncthreads();

    int cnt = s_cnt;
    float prodv = 1.0f;
    float zb = 3.0e38f;
    float w0b = 0.0f, w1b = 0.0f, w2b = 0.0f;
    int fb = 0x7FFFFFFF;

    // Phase 2: balanced, software-pipelined face loop (faces warp-uniform).
    int j = wid;
    int f = -1;
    float4 v01, v2i, hh;
    if (j < cnt) {
        f = s_list[j];
        v01 = __ldg(&g_hot[f * 4 + 1]);
        v2i = __ldg(&g_hot[f * 4 + 2]);
        hh  = __ldg(&g_hot[f * 4 + 3]);
    }
    while (f >= 0) {
        // prefetch next face while current computes
        int jn = j + 8;
        int fn = -1;
        float4 v01n, v2in, hhn;
        if (jn < cnt) {
            fn = s_list[jn];
            v01n = __ldg(&g_hot[fn * 4 + 1]);
            v2in = __ldg(&g_hot[fn * 4 + 2]);
            hhn  = __ldg(&g_hot[fn * 4 + 3]);
        }

        float w0 = ((v01.z - px) * (v2i.y - py) - (v2i.x - px) * (v01.w - py)) * v2i.z;
        float w1 = ((v2i.x - px) * (v01.y - py) - (v01.x - px) * (v2i.y - py)) * v2i.z;
        float w2 = 1.0f - w0 - w1;

        if (w0 >= 0.0f && w1 >= 0.0f && w2 >= 0.0f) {
            prodv = 0.0f;  // probf = 1 inside
            float4 zz = __ldg(&g_cold[f * 4 + 0]);
            float z = w0 * zz.x + w1 * zz.y + w2 * zz.z;
            // argmin-first semantics: smaller z, ties -> smaller face index
            if (z < zb || (z == zb && f < fb)) {
                zb = z; fb = f; w0b = w0; w1b = w1; w2b = w2;
            }
        } else if (prodv != 0.0f) {
            // lower bound on distance; if >= DLB_T, (1-probf)==1.0f exactly.
            // (also exactly covers pixels outside the 0.06-margin bbox)
            float dlb = fmaxf(fmaxf(-w0 * hh.x, -w1 * hh.y), -w2 * hh.z);
            if (dlb < DLB_T) {
                float d2 = seg_d2(px, py, v01.x, v01.y, v01.z, v01.w);
                d2 = fminf(d2, seg_d2(px, py, v01.z, v01.w, v2i.x, v2i.y));
                d2 = fminf(d2, seg_d2(px, py, v2i.x, v2i.y, v01.x, v01.y));
                prodv *= (1.0f - expf(-d2 * SIGMAINV));
            }
        }

        j = jn; f = fn; v01 = v01n; v2i = v2in; hh = hhn;
    }

    // Phase 3: combine the 8 per-warp partials (lane = pixel).
    s_z[wid][lane] = zb;
    s_f[wid][lane] = fb;
    s_w0[wid][lane] = w0b;
    s_w1[wid][lane] = w1b;
    s_w2[wid][lane] = w2b;
    s_p[wid][lane] = prodv;
    __syncthreads();

    if (wid == 0) {
#pragma unroll
        for (int k = 1; k < 8; k++) {
            float oz = s_z[k][lane];
            int of = s_f[k][lane];
            prodv *= s_p[k][lane];
            if (oz < zb || (oz == zb && of < fb)) {
                zb = oz; fb = of;
                w0b = s_w0[k][lane];
                w1b = s_w1[k][lane];
                w2b = s_w2[k][lane];
            }
        }

        float rr = 0.0f, gg = 0.0f, bc = 0.0f;
        if (fb != 0x7FFFFFFF) {
            float4 c0 = __ldg(&g_cold[fb * 4 + 1]);
            float4 c1 = __ldg(&g_cold[fb * 4 + 2]);
            float4 c2 = __ldg(&g_cold[fb * 4 + 3]);
            rr = w0b * c0.x + w1b * c1.x + w2b * c2.x;
            gg = w0b * c0.y + w1b * c1.y + w2b * c2.y;
            bc = w0b * c0.z + w1b * c1.z + w2b * c2.z;
        }

        int p = iy * HW + ix;
        out[p * 3 + 0] = rr;
        out[p * 3 + 1] = gg;
        out[p * 3 + 2] = bc;
        out[NPIX * 3 + p] = 1.0f - prodv;
    }
}

extern "C" void kernel_launch(void* const* d_in, const int* in_sizes, int n_in,
                              void* d_out, int out_size) {
    const float* pts  = (const float*)d_in[0];
    const float* cols = (const float*)d_in[1];
    const float* rot  = (const float*)d_in[2];
    const float* cpos = (const float*)d_in[3];
    const float* proj = (const float*)d_in[4];
    const int*   fcs  = (const int*)d_in[5];
    float* out = (float*)d_out;

    preproc_kernel<<<2, 256>>>(pts, cols, rot, cpos, proj, fcs, out);
    raster_kernel<<<NPIX / 32, 256>>>(out);
}

// round 9
// speedup vs baseline: 3.4251x; 1.6069x over previous
#include <cuda_runtime.h>
#include <math.h>

#define HW 128
#define NPIX (HW*HW)
#define NF 512
#define NP 256
#define SIGMAINV 7000.0f
#define BBOX_M 0.06f
#define DLB_T 0.055f

__device__ __forceinline__ float seg_d2(float px, float py, float ax, float ay,
                                        float bx, float by) {
    float abx = bx - ax, aby = by - ay;
    float apx = px - ax, apy = py - ay;
    float t = __fdividef(apx * abx + apy * aby, abx * abx + aby * aby + 1e-10f);
    t = fminf(fmaxf(t, 0.0f), 1.0f);
    float dx = apx - t * abx;
    float dy = apy - t * aby;
    return dx * dx + dy * dy;
}

// Single fused kernel. Block = 256 threads = 8 warps = one 8x4-pixel patch.
// Phase 0: block-local preprocessing: vertex transform (1/thread) + face
//          tables (2/thread) into SMEM; bbox-vs-patch ballot inline.
//          Block 0 also writes the normal1 output.
// Phase 1: deterministic compaction of survivors into s_list.
// Phase 2: warps take list entries round-robin; body is predicated with one
//          warp-uniform branch for the edge-distance path.
// Phase 3: smem reduction; warp 0 gathers winner colors + writes.
__global__ __launch_bounds__(256)
void raster_fused(float* __restrict__ out,
                  const float* __restrict__ pts,
                  const float* __restrict__ cols,
                  const float* __restrict__ rot,
                  const float* __restrict__ cpos,
                  const float* __restrict__ proj,
                  const int* __restrict__ faces) {
    __shared__ float s_vx[NP], s_vy[NP], s_cx[NP], s_cy[NP], s_cz[NP];
    __shared__ float4 s_A[NF];   // x0,y0,x1,y1
    __shared__ float4 s_B[NF];   // x2,y2,invden,h0
    __shared__ float4 s_C[NF];   // h1,h2,z0,z1
    __shared__ float s_z2[NF];
    __shared__ unsigned s_words[16];
    __shared__ int s_cnt;
    __shared__ short s_list[NF];
    __shared__ float s_rz[8][32], s_rw0[8][32], s_rw1[8][32], s_rw2[8][32], s_rp[8][32];
    __shared__ int s_rf[8][32];

    int t = threadIdx.x;
    int lane = t & 31;
    int wid = t >> 5;
    int b = blockIdx.x;
    int px0 = (b & 15) * 8;     // 16 patches across
    int py0 = (b >> 4) * 4;     // 32 patch-rows
    int ix = px0 + (lane & 7);
    int iy = py0 + (lane >> 3);

    float px = (ix + 0.5f) * (2.0f / HW) - 1.0f;
    float py = 1.0f - (iy + 0.5f) * (2.0f / HW);

    // patch NDC bounds (pixel centers)
    float xmn = (px0 + 0.5f) * (2.0f / HW) - 1.0f;
    float xmx = (px0 + 7.5f) * (2.0f / HW) - 1.0f;
    float ymx = 1.0f - (py0 + 0.5f) * (2.0f / HW);
    float ymn = 1.0f - (py0 + 3.5f) * (2.0f / HW);

    // ---- Phase 0a: per-vertex transform (1 vertex / thread) ----
    {
        float r00 = rot[0], r01 = rot[1], r02 = rot[2];
        float r10 = rot[3], r11 = rot[4], r12 = rot[5];
        float r20 = rot[6], r21 = rot[7], r22 = rot[8];
        float cx = cpos[0], cy = cpos[1], cz = cpos[2];
        float pr0 = proj[0], pr1 = proj[1], pr2 = proj[2];

        float qx = pts[t * 3 + 0] - cx;
        float qy = pts[t * 3 + 1] - cy;
        float qz = pts[t * 3 + 2] - cz;
        float X = qx * r00 + qy * r01 + qz * r02;
        float Y = qx * r10 + qy * r11 + qz * r12;
        float Z = qx * r20 + qy * r21 + qz * r22;
        s_cx[t] = X; s_cy[t] = Y; s_cz[t] = Z;
        s_vx[t] = (X * pr0) / (Z * pr2);
        s_vy[t] = (Y * pr1) / (Z * pr2);
    }
    __syncthreads();

    // ---- Phase 0b: per-face tables (2 faces / thread) + bbox ballot ----
#pragma unroll
    for (int i = 0; i < 2; i++) {
        int f = i * 256 + t;   // == i*256 + wid*32 + lane
        int i0 = faces[f * 3 + 0];
        int i1 = faces[f * 3 + 1];
        int i2 = faces[f * 3 + 2];
        float x0 = s_vx[i0], y0 = s_vy[i0];
        float x1 = s_vx[i1], y1 = s_vy[i1];
        float x2 = s_vx[i2], y2 = s_vy[i2];

        // normal z in camera space (only x,y components of edges needed)
        float e1x = s_cx[i1] - s_cx[i0], e1y = s_cy[i1] - s_cy[i0];
        float e2x = s_cx[i2] - s_cx[i0], e2y = s_cy[i2] - s_cy[i0];
        float nz = e1x * e2y - e1y * e2x;

        float area = (x1 - x0) * (y2 - y0) - (x2 - x0) * (y1 - y0);
        bool ok = (nz > 0.0f) && (fabsf(area) > 1e-10f);

        // margin bbox; poisoned when !ok so ballot rejects
        float bxm = fminf(fminf(x0, x1), x2) - BBOX_M;
        float bxM = fmaxf(fmaxf(x0, x1), x2) + BBOX_M;
        float bym = fminf(fminf(y0, y1), y2) - BBOX_M;
        float byM = fmaxf(fmaxf(y0, y1), y2) + BBOX_M;
        bool ov = ok && (bxm <= xmx) && (bxM >= xmn) && (bym <= ymx) && (byM >= ymn);
        unsigned bal = __ballot_sync(0xFFFFFFFFu, ov);
        if (lane == 0) s_words[i * 8 + wid] = bal;

        float aabs = fabsf(area);
        float L0s = (x2 - x1) * (x2 - x1) + (y2 - y1) * (y2 - y1);
        float L1s = (x0 - x2) * (x0 - x2) + (y0 - y2) * (y0 - y2);
        float L2s = (x1 - x0) * (x1 - x0) + (y1 - y0) * (y1 - y0);
        float h0 = aabs * rsqrtf(fmaxf(L0s, 1e-40f));
        float h1 = aabs * rsqrtf(fmaxf(L1s, 1e-40f));
        float h2 = aabs * rsqrtf(fmaxf(L2s, 1e-40f));

        s_A[f] = make_float4(x0, y0, x1, y1);
        s_B[f] = make_float4(x2, y2, ok ? (1.0f / area) : 0.0f, h0);
        s_C[f] = make_float4(h1, h2, s_cz[i0], s_cz[i1]);
        s_z2[f] = s_cz[i2];

        // block 0 additionally writes the normalized normals output
        if (b == 0) {
            float e1z = s_cz[i1] - s_cz[i0];
            float e2z = s_cz[i2] - s_cz[i0];
            float nxx = e1y * e2z - e1z * e2y;
            float nyy = e1z * e2x - e1x * e2z;
            float nlen = sqrtf(nxx * nxx + nyy * nyy + nz * nz + 1e-8f);
            float ninv = 1.0f / (nlen + 1e-15f);
            out[NPIX * 4 + f * 3 + 0] = nxx * ninv;
            out[NPIX * 4 + f * 3 + 1] = nyy * ninv;
            out[NPIX * 4 + f * 3 + 2] = nz * ninv;
        }
    }
    __syncthreads();

    // ---- Phase 1: deterministic compaction by warp 0 ----
    if (wid == 0) {
        unsigned wv = (lane < 16) ? s_words[lane] : 0u;
        int c = __popc(wv);
        int s = c;
#pragma unroll
        for (int off = 1; off < 32; off <<= 1) {
            int n = __shfl_up_sync(0xFFFFFFFFu, s, off);
            if (lane >= off) s += n;
        }
        if (lane == 15) s_cnt = s;
        if (lane < 16) {
            int pos = s - c;
            int base = lane * 32;
            unsigned m = wv;
            while (m) {
                int bit = __ffs(m) - 1;
                m &= m - 1;
                s_list[pos++] = (short)(base + bit);
            }
        }
    }
    __syncthreads();

    int cnt = s_cnt;
    float prodv = 1.0f;
    float zb = 3.0e38f;
    float w0b = 0.0f, w1b = 0.0f, w2b = 0.0f;
    int fb = 0x7FFFFFFF;

    // ---- Phase 2: balanced, predicated face loop ----
    for (int j = wid; j < cnt; j += 8) {
        int f = s_list[j];
        float4 A = s_A[f];
        float4 B = s_B[f];
        float4 C = s_C[f];
        float z2v = s_z2[f];

        float w0 = ((A.z - px) * (B.y - py) - (B.x - px) * (A.w - py)) * B.z;
        float w1 = ((B.x - px) * (A.y - py) - (A.x - px) * (B.y - py)) * B.z;
        float w2 = 1.0f - w0 - w1;

        bool inside = (w0 >= 0.0f) && (w1 >= 0.0f) && (w2 >= 0.0f);
        float z = w0 * C.z + w1 * C.w + w2 * z2v;
        // argmin-first semantics: smaller z, ties -> smaller face index
        bool better = inside && (z < zb || (z == zb && f < fb));
        zb  = better ? z  : zb;
        fb  = better ? f  : fb;
        w0b = better ? w0 : w0b;
        w1b = better ? w1 : w1b;
        w2b = better ? w2 : w2b;
        prodv = inside ? 0.0f : prodv;   // probf = 1 inside

        // lower bound on distance; if >= DLB_T, (1-probf)==1.0f exactly
        float dlb = fmaxf(fmaxf(-w0 * B.w, -w1 * C.x), -w2 * C.y);
        bool need = (!inside) && (prodv != 0.0f) && (dlb < DLB_T);
        if (__any_sync(0xFFFFFFFFu, need)) {
            float d2 = seg_d2(px, py, A.x, A.y, A.z, A.w);
            d2 = fminf(d2, seg_d2(px, py, A.z, A.w, B.x, B.y));
            d2 = fminf(d2, seg_d2(px, py, B.x, B.y, A.x, A.y));
            float e = __expf(-d2 * SIGMAINV);
            prodv = need ? prodv * (1.0f - e) : prodv;
        }
    }

    // ---- Phase 3: combine the 8 per-warp partials (lane = pixel) ----
    s_rz[wid][lane] = zb;
    s_rf[wid][lane] = fb;
    s_rw0[wid][lane] = w0b;
    s_rw1[wid][lane] = w1b;
    s_rw2[wid][lane] = w2b;
    s_rp[wid][lane] = prodv;
    __syncthreads();

    if (wid == 0) {
#pragma unroll
        for (int k = 1; k < 8; k++) {
            float oz = s_rz[k][lane];
            int of = s_rf[k][lane];
            prodv *= s_rp[k][lane];
            if (oz < zb || (oz == zb && of < fb)) {
                zb = oz; fb = of;
                w0b = s_rw0[k][lane];
                w1b = s_rw1[k][lane];
                w2b = s_rw2[k][lane];
            }
        }

        float rr = 0.0f, gg = 0.0f, bc = 0.0f;
        if (fb != 0x7FFFFFFF) {
            int i0 = faces[fb * 3 + 0];
            int i1 = faces[fb * 3 + 1];
            int i2 = faces[fb * 3 + 2];
            rr = w0b * cols[i0 * 3 + 0] + w1b * cols[i1 * 3 + 0] + w2b * cols[i2 * 3 + 0];
            gg = w0b * cols[i0 * 3 + 1] + w1b * cols[i1 * 3 + 1] + w2b * cols[i2 * 3 + 1];
            bc = w0b * cols[i0 * 3 + 2] + w1b * cols[i1 * 3 + 2] + w2b * cols[i2 * 3 + 2];
        }

        int p = iy * HW + ix;
        out[p * 3 + 0] = rr;
        out[p * 3 + 1] = gg;
        out[p * 3 + 2] = bc;
        out[NPIX * 3 + p] = 1.0f - prodv;
    }
}

extern "C" void kernel_launch(void* const* d_in, const int* in_sizes, int n_in,
                              void* d_out, int out_size) {
    const float* pts  = (const float*)d_in[0];
    const float* cols = (const float*)d_in[1];
    const float* rot  = (const float*)d_in[2];
    const float* cpos = (const float*)d_in[3];
    const float* proj = (const float*)d_in[4];
    const int*   fcs  = (const int*)d_in[5];
    float* out = (float*)d_out;

    raster_fused<<<NPIX / 32, 256>>>(out, pts, cols, rot, cpos, proj, fcs);
}

// round 10
// speedup vs baseline: 3.4850x; 1.0175x over previous
#include <cuda_runtime.h>
#include <math.h>

#define HW 128
#define NPIX (HW*HW)
#define NF 512
#define NP 256
#define SIGMAINV 7000.0f
#define BBOX_M 0.06f
#define DLB_T 0.055f

__device__ __forceinline__ float seg_d2(float px, float py, float ax, float ay,
                                        float bx, float by) {
    float abx = bx - ax, aby = by - ay;
    float apx = px - ax, apy = py - ay;
    float t = __fdividef(apx * abx + apy * aby, abx * abx + aby * aby + 1e-10f);
    t = fminf(fmaxf(t, 0.0f), 1.0f);
    float dx = apx - t * abx;
    float dy = apy - t * aby;
    return dx * dx + dy * dy;
}

// Single fused kernel. Block = 256 threads = 8 warps = one 8x4-pixel patch.
// Phase 0: block-local preprocessing: vertex transform (1/thread) + face
//          tables (2/thread) into SMEM; bbox-vs-patch ballot inline.
//          Block 0 also writes the normal1 output.
// Phase 1: deterministic compaction of survivors into s_list.
// Phase 2: warps take list entries round-robin; body is predicated with one
//          warp-uniform branch for the edge-distance path.
// Phase 3: smem reduction; warp 0 gathers winner colors + writes.
__global__ __launch_bounds__(256)
void raster_fused(float* __restrict__ out,
                  const float* __restrict__ pts,
                  const float* __restrict__ cols,
                  const float* __restrict__ rot,
                  const float* __restrict__ cpos,
                  const float* __restrict__ proj,
                  const int* __restrict__ faces) {
    __shared__ float s_vx[NP], s_vy[NP], s_cx[NP], s_cy[NP], s_cz[NP];
    __shared__ float4 s_A[NF];   // x0,y0,x1,y1
    __shared__ float4 s_B[NF];   // x2,y2,invden,h0
    __shared__ float4 s_C[NF];   // h1,h2,z0,z1
    __shared__ float s_z2[NF];
    __shared__ unsigned s_words[16];
    __shared__ int s_cnt;
    __shared__ short s_list[NF];
    __shared__ float s_rz[8][32], s_rw0[8][32], s_rw1[8][32], s_rw2[8][32], s_rp[8][32];
    __shared__ int s_rf[8][32];

    int t = threadIdx.x;
    int lane = t & 31;
    int wid = t >> 5;
    int b = blockIdx.x;
    int px0 = (b & 15) * 8;     // 16 patches across
    int py0 = (b >> 4) * 4;     // 32 patch-rows
    int ix = px0 + (lane & 7);
    int iy = py0 + (lane >> 3);

    float px = (ix + 0.5f) * (2.0f / HW) - 1.0f;
    float py = 1.0f - (iy + 0.5f) * (2.0f / HW);

    // patch NDC bounds (pixel centers)
    float xmn = (px0 + 0.5f) * (2.0f / HW) - 1.0f;
    float xmx = (px0 + 7.5f) * (2.0f / HW) - 1.0f;
    float ymx = 1.0f - (py0 + 0.5f) * (2.0f / HW);
    float ymn = 1.0f - (py0 + 3.5f) * (2.0f / HW);

    // ---- Phase 0a: per-vertex transform (1 vertex / thread) ----
    {
        float r00 = rot[0], r01 = rot[1], r02 = rot[2];
        float r10 = rot[3], r11 = rot[4], r12 = rot[5];
        float r20 = rot[6], r21 = rot[7], r22 = rot[8];
        float cx = cpos[0], cy = cpos[1], cz = cpos[2];
        float pr0 = proj[0], pr1 = proj[1], pr2 = proj[2];

        float qx = pts[t * 3 + 0] - cx;
        float qy = pts[t * 3 + 1] - cy;
        float qz = pts[t * 3 + 2] - cz;
        float X = qx * r00 + qy * r01 + qz * r02;
        float Y = qx * r10 + qy * r11 + qz * r12;
        float Z = qx * r20 + qy * r21 + qz * r22;
        s_cx[t] = X; s_cy[t] = Y; s_cz[t] = Z;
        s_vx[t] = (X * pr0) / (Z * pr2);
        s_vy[t] = (Y * pr1) / (Z * pr2);
    }
    __syncthreads();

    // ---- Phase 0b: per-face tables (2 faces / thread) + bbox ballot ----
#pragma unroll
    for (int i = 0; i < 2; i++) {
        int f = i * 256 + t;   // == i*256 + wid*32 + lane
        int i0 = faces[f * 3 + 0];
        int i1 = faces[f * 3 + 1];
        int i2 = faces[f * 3 + 2];
        float x0 = s_vx[i0], y0 = s_vy[i0];
        float x1 = s_vx[i1], y1 = s_vy[i1];
        float x2 = s_vx[i2], y2 = s_vy[i2];

        // normal z in camera space (only x,y components of edges needed)
        float e1x = s_cx[i1] - s_cx[i0], e1y = s_cy[i1] - s_cy[i0];
        float e2x = s_cx[i2] - s_cx[i0], e2y = s_cy[i2] - s_cy[i0];
        float nz = e1x * e2y - e1y * e2x;

        float area = (x1 - x0) * (y2 - y0) - (x2 - x0) * (y1 - y0);
        bool ok = (nz > 0.0f) && (fabsf(area) > 1e-10f);

        // margin bbox; poisoned when !ok so ballot rejects
        float bxm = fminf(fminf(x0, x1), x2) - BBOX_M;
        float bxM = fmaxf(fmaxf(x0, x1), x2) + BBOX_M;
        float bym = fminf(fminf(y0, y1), y2) - BBOX_M;
        float byM = fmaxf(fmaxf(y0, y1), y2) + BBOX_M;
        bool ov = ok && (bxm <= xmx) && (bxM >= xmn) && (bym <= ymx) && (byM >= ymn);
        unsigned bal = __ballot_sync(0xFFFFFFFFu, ov);
        if (lane == 0) s_words[i * 8 + wid] = bal;

        float aabs = fabsf(area);
        float L0s = (x2 - x1) * (x2 - x1) + (y2 - y1) * (y2 - y1);
        float L1s = (x0 - x2) * (x0 - x2) + (y0 - y2) * (y0 - y2);
        float L2s = (x1 - x0) * (x1 - x0) + (y1 - y0) * (y1 - y0);
        float h0 = aabs * rsqrtf(fmaxf(L0s, 1e-40f));
        float h1 = aabs * rsqrtf(fmaxf(L1s, 1e-40f));
        float h2 = aabs * rsqrtf(fmaxf(L2s, 1e-40f));

        s_A[f] = make_float4(x0, y0, x1, y1);
        s_B[f] = make_float4(x2, y2, ok ? (1.0f / area) : 0.0f, h0);
        s_C[f] = make_float4(h1, h2, s_cz[i0], s_cz[i1]);
        s_z2[f] = s_cz[i2];

        // block 0 additionally writes the normalized normals output
        if (b == 0) {
            float e1z = s_cz[i1] - s_cz[i0];
            float e2z = s_cz[i2] - s_cz[i0];
            float nxx = e1y * e2z - e1z * e2y;
            float nyy = e1z * e2x - e1x * e2z;
            float nlen = sqrtf(nxx * nxx + nyy * nyy + nz * nz + 1e-8f);
            float ninv = 1.0f / (nlen + 1e-15f);
            out[NPIX * 4 + f * 3 + 0] = nxx * ninv;
            out[NPIX * 4 + f * 3 + 1] = nyy * ninv;
            out[NPIX * 4 + f * 3 + 2] = nz * ninv;
        }
    }
    __syncthreads();

    // ---- Phase 1: deterministic compaction by warp 0 ----
    if (wid == 0) {
        unsigned wv = (lane < 16) ? s_words[lane] : 0u;
        int c = __popc(wv);
        int s = c;
#pragma unroll
        for (int off = 1; off < 32; off <<= 1) {
            int n = __shfl_up_sync(0xFFFFFFFFu, s, off);
            if (lane >= off) s += n;
        }
        if (lane == 15) s_cnt = s;
        if (lane < 16) {
            int pos = s - c;
            int base = lane * 32;
            unsigned m = wv;
            while (m) {
                int bit = __ffs(m) - 1;
                m &= m - 1;
                s_list[pos++] = (short)(base + bit);
            }
        }
    }
    __syncthreads();

    int cnt = s_cnt;
    float prodv = 1.0f;
    float zb = 3.0e38f;
    float w0b = 0.0f, w1b = 0.0f, w2b = 0.0f;
    int fb = 0x7FFFFFFF;

    // ---- Phase 2: balanced, predicated face loop ----
    for (int j = wid; j < cnt; j += 8) {
        int f = s_list[j];
        float4 A = s_A[f];
        float4 B = s_B[f];
        float4 C = s_C[f];
        float z2v = s_z2[f];

        float w0 = ((A.z - px) * (B.y - py) - (B.x - px) * (A.w - py)) * B.z;
        float w1 = ((B.x - px) * (A.y - py) - (A.x - px) * (B.y - py)) * B.z;
        float w2 = 1.0f - w0 - w1;

        bool inside = (w0 >= 0.0f) && (w1 >= 0.0f) && (w2 >= 0.0f);
        float z = w0 * C.z + w1 * C.w + w2 * z2v;
        // argmin-first semantics: smaller z, ties -> smaller face index
        bool better = inside && (z < zb || (z == zb && f < fb));
        zb  = better ? z  : zb;
        fb  = better ? f  : fb;
        w0b = better ? w0 : w0b;
        w1b = better ? w1 : w1b;
        w2b = better ? w2 : w2b;
        prodv = inside ? 0.0f : prodv;   // probf = 1 inside

        // lower bound on distance; if >= DLB_T, (1-probf)==1.0f exactly
        float dlb = fmaxf(fmaxf(-w0 * B.w, -w1 * C.x), -w2 * C.y);
        bool need = (!inside) && (prodv != 0.0f) && (dlb < DLB_T);
        if (__any_sync(0xFFFFFFFFu, need)) {
            float d2 = seg_d2(px, py, A.x, A.y, A.z, A.w);
            d2 = fminf(d2, seg_d2(px, py, A.z, A.w, B.x, B.y));
            d2 = fminf(d2, seg_d2(px, py, B.x, B.y, A.x, A.y));
            float e = __expf(-d2 * SIGMAINV);
            prodv = need ? prodv * (1.0f - e) : prodv;
        }
    }

    // ---- Phase 3: combine the 8 per-warp partials (lane = pixel) ----
    s_rz[wid][lane] = zb;
    s_rf[wid][lane] = fb;
    s_rw0[wid][lane] = w0b;
    s_rw1[wid][lane] = w1b;
    s_rw2[wid][lane] = w2b;
    s_rp[wid][lane] = prodv;
    __syncthreads();

    if (wid == 0) {
#pragma unroll
        for (int k = 1; k < 8; k++) {
            float oz = s_rz[k][lane];
            int of = s_rf[k][lane];
            prodv *= s_rp[k][lane];
            if (oz < zb || (oz == zb && of < fb)) {
                zb = oz; fb = of;
                w0b = s_rw0[k][lane];
                w1b = s_rw1[k][lane];
                w2b = s_rw2[k][lane];
            }
        }

        float rr = 0.0f, gg = 0.0f, bc = 0.0f;
        if (fb != 0x7FFFFFFF) {
            int i0 = faces[fb * 3 + 0];
            int i1 = faces[fb * 3 + 1];
            int i2 = faces[fb * 3 + 2];
            rr = w0b * cols[i0 * 3 + 0] + w1b * cols[i1 * 3 + 0] + w2b * cols[i2 * 3 + 0];
            gg = w0b * cols[i0 * 3 + 1] + w1b * cols[i1 * 3 + 1] + w2b * cols[i2 * 3 + 1];
            bc = w0b * cols[i0 * 3 + 2] + w1b * cols[i1 * 3 + 2] + w2b * cols[i2 * 3 + 2];
        }

        int p = iy * HW + ix;
        out[p * 3 + 0] = rr;
        out[p * 3 + 1] = gg;
        out[p * 3 + 2] = bc;
        out[NPIX * 3 + p] = 1.0f - prodv;
    }
}

extern "C" void kernel_launch(void* const* d_in, const int* in_sizes, int n_in,
                              void* d_out, int out_size) {
    const float* pts  = (const float*)d_in[0];
    const float* cols = (const float*)d_in[1];
    const float* rot  = (const float*)d_in[2];
    const float* cpos = (const float*)d_in[3];
    const float* proj = (const float*)d_in[4];
    const int*   fcs  = (const int*)d_in[5];
    float* out = (float*)d_out;

    raster_fused<<<NPIX / 32, 256>>>(out, pts, cols, rot, cpos, proj, fcs);
}